// round 7
// baseline (speedup 1.0000x reference)
#include <cuda_runtime.h>
#include <cstdint>

#define NB 8
#define LQ 256
#define LK 256
#define HH 256
#define DV 256
#define MASK_VALUE -1000000.0f

// Scratch (allocation-free rule: device globals)
__device__ float g_Qp[NB * LQ * HH];
__device__ float g_Kp[NB * LK * HH];
__device__ float g_S[NB * LQ * LK];

__device__ __forceinline__ float tanh_fast(float x) {
    float y;
    asm("tanh.approx.f32 %0, %1;" : "=f"(y) : "f"(x));
    return y;
}

__device__ __forceinline__ uint32_t f2tf(float x) {
    uint32_t r;
    asm("cvt.rna.tf32.f32 %0, %1;" : "=r"(r) : "f"(x));
    return r;
}

__device__ __forceinline__ uint4 tf4(float4 v) {
    return make_uint4(f2tf(v.x), f2tf(v.y), f2tf(v.z), f2tf(v.w));
}

// D += A(16x8,row) * B(8x8,col)  in tf32, fp32 accum
__device__ __forceinline__ void mma8(float* d, const uint32_t* a, const uint32_t* b) {
    asm("mma.sync.aligned.m16n8k8.row.col.f32.tf32.tf32.f32 "
        "{%0,%1,%2,%3}, {%4,%5,%6,%7}, {%8,%9}, {%0,%1,%2,%3};"
        : "+f"(d[0]), "+f"(d[1]), "+f"(d[2]), "+f"(d[3])
        : "r"(a[0]), "r"(a[1]), "r"(a[2]), "r"(a[3]), "r"(b[0]), "r"(b[1]));
}

#define TS 36  // smem stride, k-contiguous tiles (fragment LDS conflict-free)
#define VS 35  // smem stride, transposed V tile (<=2-way)

// ---------------------------------------------------------------------------
// Projection NT GEMM (tf32, split-K): C[m][n] = sum_k X[m][k]*W[n][k]
// CTA 32m x 32n, 256 threads = 8 warps in 2 k-groups (k 0..127 / 128..255).
// Each group: private double tiles, 4 chunks of kc=32; warp tile 16x16.
// Partials reduced through smem. grid (8, 64, 2) = 1024 blocks.
// ---------------------------------------------------------------------------
__global__ void __launch_bounds__(256) proj_kernel(
    const float* __restrict__ Xq, const float* __restrict__ Wq,
    const float* __restrict__ Xk, const float* __restrict__ Wk) {
    const float* X;
    const float* W;
    float* C;
    if (blockIdx.z == 0) { X = Xq; W = Wq; C = g_Qp; }
    else                 { X = Xk; W = Wk; C = g_Kp; }

    __shared__ uint32_t Xs[2][32 * TS];
    __shared__ uint32_t Ws[2][32 * TS];
    __shared__ float red[4][32][8];

    const int tid = threadIdx.x;
    const int lane = tid & 31;
    const int warp = tid >> 5;
    const int g = warp >> 2;        // k-group 0/1
    const int s = warp & 3;         // sub-tile within group
    const int wm = (s & 1) * 16;
    const int wn = (s >> 1) * 16;
    const int gid = lane >> 2;
    const int tig = lane & 3;
    const int m0 = blockIdx.y * 32;
    const int n0 = blockIdx.x * 32;

    // staging: threads 0-127 fill group-0 tiles, 128-255 group-1 tiles
    const int sg = tid >> 7;
    const int st = tid & 127;
    const int r0 = st >> 3;         // 0..15
    const int c4 = st & 7;          // k-float4 within chunk

    float d[2][4] = {};

    for (int it = 0; it < 4; it++) {
        const int kb = (sg * 4 + it) * 32;
        uint4 x0 = tf4(*(const float4*)&X[(m0 + r0) * 256 + kb + c4 * 4]);
        uint4 x1 = tf4(*(const float4*)&X[(m0 + r0 + 16) * 256 + kb + c4 * 4]);
        uint4 w0 = tf4(*(const float4*)&W[(n0 + r0) * 256 + kb + c4 * 4]);
        uint4 w1 = tf4(*(const float4*)&W[(n0 + r0 + 16) * 256 + kb + c4 * 4]);
        *(uint4*)&Xs[sg][r0 * TS + c4 * 4] = x0;
        *(uint4*)&Xs[sg][(r0 + 16) * TS + c4 * 4] = x1;
        *(uint4*)&Ws[sg][r0 * TS + c4 * 4] = w0;
        *(uint4*)&Ws[sg][(r0 + 16) * TS + c4 * 4] = w1;
        __syncthreads();

        const uint32_t* XB = Xs[g];
        const uint32_t* WB = Ws[g];
        #pragma unroll
        for (int ks = 0; ks < 4; ks++) {
            const int kk = ks * 8;
            uint32_t a[4], b0[2], b1[2];
            const int r = wm + gid;
            a[0] = XB[r * TS + kk + tig];
            a[1] = XB[(r + 8) * TS + kk + tig];
            a[2] = XB[r * TS + kk + tig + 4];
            a[3] = XB[(r + 8) * TS + kk + tig + 4];
            const int n = wn + gid;
            b0[0] = WB[n * TS + kk + tig];
            b0[1] = WB[n * TS + kk + tig + 4];
            b1[0] = WB[(n + 8) * TS + kk + tig];
            b1[1] = WB[(n + 8) * TS + kk + tig + 4];
            mma8(d[0], a, b0);
            mma8(d[1], a, b1);
        }
        __syncthreads();
    }

    // split-K reduction: group 1 -> smem, group 0 adds and writes
    if (g == 1) {
        *(float4*)&red[s][lane][0] = make_float4(d[0][0], d[0][1], d[0][2], d[0][3]);
        *(float4*)&red[s][lane][4] = make_float4(d[1][0], d[1][1], d[1][2], d[1][3]);
    }
    __syncthreads();
    if (g == 0) {
        const float* rp = red[s][lane];
        #pragma unroll
        for (int e = 0; e < 4; e++) { d[0][e] += rp[e]; d[1][e] += rp[4 + e]; }
        const int row = m0 + wm + gid;
        #pragma unroll
        for (int jn = 0; jn < 2; jn++) {
            const int col = n0 + wn + jn * 8 + tig * 2;
            *(float2*)&C[row * 256 + col] = make_float2(d[jn][0], d[jn][1]);
            *(float2*)&C[(row + 8) * 256 + col] = make_float2(d[jn][2], d[jn][3]);
        }
    }
}

// ---------------------------------------------------------------------------
// Scores: S[b][q][k] = sum_h Wv[h] * tanh(Qp[b][q][h] + Kp[b][k][h]),
// masked to MASK_VALUE where k >= valid_len[b]. Fully-masked 32x32 tiles skip
// all compute. MUFU-bound by design.
// ---------------------------------------------------------------------------
__global__ void scores_kernel(const float* __restrict__ Wv,
                              const int* __restrict__ vlens) {
    const int b = blockIdx.z;
    const int q0 = blockIdx.y * 32;
    const int k0 = blockIdx.x * 32;
    const int tid = threadIdx.x;
    const int tx = tid & 15;
    const int ty = tid >> 4;
    const int vl = vlens[b];
    float* S = g_S + b * LQ * LK;

    if (k0 >= vl) {
        const float2 mv = make_float2(MASK_VALUE, MASK_VALUE);
        #pragma unroll
        for (int i = 0; i < 2; i++)
            *(float2*)&S[(q0 + ty * 2 + i) * LK + k0 + tx * 2] = mv;
        return;
    }

    __shared__ float Qs[64][34];
    __shared__ float Ks[64][34];
    __shared__ float sWv[256];

    sWv[tid] = Wv[tid];

    const float* Qb = g_Qp + (b * LQ + q0) * HH;
    const float* Kb = g_Kp + (b * LK + k0) * HH;

    float a00 = 0.f, a01 = 0.f, a10 = 0.f, a11 = 0.f;

    for (int h0 = 0; h0 < HH; h0 += 64) {
        #pragma unroll
        for (int idx = tid; idx < 32 * 64; idx += 256) {
            int r = idx >> 6;
            int h = idx & 63;
            Qs[h][r] = Qb[r * HH + h0 + h];
            Ks[h][r] = Kb[r * HH + h0 + h];
        }
        __syncthreads();
        #pragma unroll 8
        for (int h = 0; h < 64; h++) {
            float2 qv = *(const float2*)&Qs[h][ty * 2];
            float2 kv = *(const float2*)&Ks[h][tx * 2];
            float wv = sWv[h0 + h];
            a00 += wv * tanh_fast(qv.x + kv.x);
            a01 += wv * tanh_fast(qv.x + kv.y);
            a10 += wv * tanh_fast(qv.y + kv.x);
            a11 += wv * tanh_fast(qv.y + kv.y);
        }
        __syncthreads();
    }

    const int kA = k0 + tx * 2;
    const int kB = kA + 1;
    const int qA = q0 + ty * 2;
    const int qB = qA + 1;
    S[qA * LK + kA] = (kA < vl) ? a00 : MASK_VALUE;
    S[qA * LK + kB] = (kB < vl) ? a01 : MASK_VALUE;
    S[qB * LK + kA] = (kA < vl) ? a10 : MASK_VALUE;
    S[qB * LK + kB] = (kB < vl) ? a11 : MASK_VALUE;
}

// ---------------------------------------------------------------------------
// Softmax over axis=1 (QUERY axis) per (b, k) column — reference quirk.
// ---------------------------------------------------------------------------
__global__ void softmax_kernel() {
    const int b = blockIdx.y;
    const int tx = threadIdx.x & 31;
    const int ty = threadIdx.x >> 5;  // 0..7
    const int k = blockIdx.x * 32 + tx;
    float* S = g_S + b * LQ * LK;

    float vals[32];
    float m = -3.4e38f;
    #pragma unroll
    for (int i = 0; i < 32; i++) {
        vals[i] = S[(i * 8 + ty) * LK + k];
        m = fmaxf(m, vals[i]);
    }

    __shared__ float red[8][33];
    red[ty][tx] = m;
    __syncthreads();
    float M = red[0][tx];
    #pragma unroll
    for (int t = 1; t < 8; t++) M = fmaxf(M, red[t][tx]);
    __syncthreads();

    float s = 0.f;
    #pragma unroll
    for (int i = 0; i < 32; i++) {
        vals[i] = __expf(vals[i] - M);
        s += vals[i];
    }
    red[ty][tx] = s;
    __syncthreads();
    float SUM = 0.f;
    #pragma unroll
    for (int t = 0; t < 8; t++) SUM += red[t][tx];

    const float inv = 1.0f / SUM;
    #pragma unroll
    for (int i = 0; i < 32; i++)
        S[(i * 8 + ty) * LK + k] = vals[i] * inv;
}

// ---------------------------------------------------------------------------
// Output NN GEMM (tf32, split-K): out[b][q][d] = sum_k A[b][q][k]*V[b][k][d]
// Same structure as proj; V staged transposed [d][k] (stride 35).
// grid (8, 8, 8) = 512 blocks.
// ---------------------------------------------------------------------------
__global__ void __launch_bounds__(256) out_kernel(
    const float* __restrict__ Vv, float* __restrict__ out) {
    const int b = blockIdx.z;
    const int q0 = blockIdx.y * 32;
    const int d0 = blockIdx.x * 32;
    const int tid = threadIdx.x;
    const int lane = tid & 31;
    const int warp = tid >> 5;
    const int g = warp >> 2;
    const int s = warp & 3;
    const int wq = (s & 1) * 16;
    const int wn = (s >> 1) * 16;
    const int gid = lane >> 2;
    const int tig = lane & 3;

    const float* A = g_S + b * LQ * LK;
    const float* V = Vv + b * LK * DV;

    __shared__ uint32_t As[2][32 * TS];
    __shared__ uint32_t Vs[2][32 * VS];
    __shared__ float red[4][32][8];

    const int sg = tid >> 7;
    const int st = tid & 127;
    const int r0 = st >> 3;
    const int c4 = st & 7;

    float d[2][4] = {};

    for (int it = 0; it < 4; it++) {
        const int kb = (sg * 4 + it) * 32;
        uint4 a0 = tf4(*(const float4*)&A[(q0 + r0) * LK + kb + c4 * 4]);
        uint4 a1 = tf4(*(const float4*)&A[(q0 + r0 + 16) * LK + kb + c4 * 4]);
        float4 v0 = *(const float4*)&V[(kb + r0) * DV + d0 + c4 * 4];
        float4 v1 = *(const float4*)&V[(kb + r0 + 16) * DV + d0 + c4 * 4];
        *(uint4*)&As[sg][r0 * TS + c4 * 4] = a0;
        *(uint4*)&As[sg][(r0 + 16) * TS + c4 * 4] = a1;
        {   // transposed store of V: Vs[d][k]
            uint32_t* VB = Vs[sg];
            const int dc = c4 * 4;
            VB[(dc + 0) * VS + r0] = f2tf(v0.x);
            VB[(dc + 1) * VS + r0] = f2tf(v0.y);
            VB[(dc + 2) * VS + r0] = f2tf(v0.z);
            VB[(dc + 3) * VS + r0] = f2tf(v0.w);
            VB[(dc + 0) * VS + r0 + 16] = f2tf(v1.x);
            VB[(dc + 1) * VS + r0 + 16] = f2tf(v1.y);
            VB[(dc + 2) * VS + r0 + 16] = f2tf(v1.z);
            VB[(dc + 3) * VS + r0 + 16] = f2tf(v1.w);
        }
        __syncthreads();

        const uint32_t* AB = As[g];
        const uint32_t* VB = Vs[g];
        #pragma unroll
        for (int ks = 0; ks < 4; ks++) {
            const int kk = ks * 8;
            uint32_t a[4], b0[2], b1[2];
            const int r = wq + gid;
            a[0] = AB[r * TS + kk + tig];
            a[1] = AB[(r + 8) * TS + kk + tig];
            a[2] = AB[r * TS + kk + tig + 4];
            a[3] = AB[(r + 8) * TS + kk + tig + 4];
            const int n = wn + gid;
            b0[0] = VB[n * VS + kk + tig];
            b0[1] = VB[n * VS + kk + tig + 4];
            b1[0] = VB[(n + 8) * VS + kk + tig];
            b1[1] = VB[(n + 8) * VS + kk + tig + 4];
            mma8(d[0], a, b0);
            mma8(d[1], a, b1);
        }
        __syncthreads();
    }

    if (g == 1) {
        *(float4*)&red[s][lane][0] = make_float4(d[0][0], d[0][1], d[0][2], d[0][3]);
        *(float4*)&red[s][lane][4] = make_float4(d[1][0], d[1][1], d[1][2], d[1][3]);
    }
    __syncthreads();
    if (g == 0) {
        const float* rp = red[s][lane];
        #pragma unroll
        for (int e = 0; e < 4; e++) { d[0][e] += rp[e]; d[1][e] += rp[4 + e]; }
        float* O = out + b * LQ * DV;
        const int row = q0 + wq + gid;
        #pragma unroll
        for (int jn = 0; jn < 2; jn++) {
            const int col = d0 + wn + jn * 8 + tig * 2;
            *(float2*)&O[row * DV + col] = make_float2(d[jn][0], d[jn][1]);
            *(float2*)&O[(row + 8) * DV + col] = make_float2(d[jn][2], d[jn][3]);
        }
    }
}

extern "C" void kernel_launch(void* const* d_in, const int* in_sizes, int n_in,
                              void* d_out, int out_size) {
    const float* queries    = (const float*)d_in[0];
    const float* keyes      = (const float*)d_in[1];
    const float* values     = (const float*)d_in[2];
    const int*   valid_lens = (const int*)d_in[3];
    const float* W_q        = (const float*)d_in[4];
    const float* W_k        = (const float*)d_in[5];
    const float* W_v        = (const float*)d_in[6];
    float* out = (float*)d_out;

    proj_kernel<<<dim3(8, 64, 2), 256>>>(queries, W_q, keyes, W_k);
    scores_kernel<<<dim3(8, 8, 8), 256>>>(W_v, valid_lens);
    softmax_kernel<<<dim3(8, 8), 256>>>();
    out_kernel<<<dim3(8, 8, 8), 256>>>(values, out);
}